// round 16
// baseline (speedup 1.0000x reference)
#include <cuda_runtime.h>
#include <cstdint>
#include <cfloat>

#define NN 50000
#define NE 500000
#define HID 128
#define HC 256

// ---------------- scratch (static device globals; no allocation) -------------
__device__ float g_xa[(size_t)NN * HID];
__device__ float g_xb[(size_t)NN * HID];
__device__ float g_c1[(size_t)NN * 384];   // [z(256) | skip(128)]
__device__ float g_y[(size_t)NN * HC];     // aggregated weighted x per head
__device__ float g_c2[(size_t)NN * HID];   // y @ W2cat
__device__ float g_bx[(size_t)NN * 2];     // vb_h . x_n  (per-source bias dot)
__device__ float g_sv[(size_t)NN * 2];
__device__ int   g_cnt[NN];
__device__ int   g_off[NN];
__device__ int   g_cur[NN];
__device__ int   g_srcs[NE];
__device__ float g_eas[NE];
__device__ int   g_perm[NN];               // nodes sorted by in-degree
__device__ int   g_dh[256];                // degree histogram / offsets

// precomputed (weights are launch-constant)
__device__ float g_w1[3 * HID * 384];      // [M_0 | M_1 | Wskip]
__device__ float g_w2[3 * HC * HID];       // 0.5*[Wv_0 ; Wv_1]
__device__ float g_b1[3 * 384];            // [0(256) | bskip]
__device__ float g_uqe[3 * 2 * HID];       // Wq_h @ We_h
__device__ float g_va[3 * 2 * HID];        // Wq_h @ bk_h
__device__ float g_vb[3 * 2 * HID];        // Wk_h @ bq_h
__device__ float g_c0[3 * 2];              // bq_h . bk_h
__device__ float g_c1s[3 * 2];             // bq_h . We_h
__device__ float g_bvm[3 * HID];           // 0.5*(bv_0 + bv_1)
__device__ float g_bzero[384];             // stays zero

#define RSQRT_D 0.08838834764831845f /* 1/sqrt(128) */

__device__ __forceinline__ float dot4(float4 a, float4 b) {
    return a.x * b.x + a.y * b.y + a.z * b.z + a.w * b.w;
}

// ---------------- GEMM: C[M,Nc] = A[M,K] @ W[K,Nc] + bias --------------------
// (R12 configuration — measured best, frozen)
__global__ __launch_bounds__(256, 2)
void gemm128(const float* __restrict__ A, const float* __restrict__ W,
             const float* __restrict__ bias, float* __restrict__ C,
             int M, int Nc, int K) {
    __shared__ float As[2][16][132];
    __shared__ float Bs[2][16][132];
    int t    = threadIdx.x;
    int lane = t & 31, warp = t >> 5;
    int warpM = warp >> 1, warpN = warp & 1;
    int lr = lane >> 3, lc = lane & 7;
    int m0 = blockIdx.y * 128, n0 = blockIdx.x * 128;
    int nTiles = K >> 4;

    unsigned long long acc[2][2][4][2];
#pragma unroll
    for (int qm = 0; qm < 2; qm++)
#pragma unroll
        for (int qn = 0; qn < 2; qn++)
#pragma unroll
            for (int i = 0; i < 4; i++) {
                acc[qm][qn][i][0] = 0ull;
                acc[qm][qn][i][1] = 0ull;
            }

    int aRow[2], aKq[2], bK[2], bNq[2];
#pragma unroll
    for (int rep = 0; rep < 2; rep++) {
        int idx = rep * 256 + t;
        aRow[rep] = idx >> 2;
        aKq[rep]  = (idx & 3) * 4;
        bK[rep]   = idx >> 5;
        bNq[rep]  = (idx & 31) * 4;
    }

    float4 rA[2], rB[2];
#pragma unroll
    for (int rep = 0; rep < 2; rep++) {
        rA[rep] = (m0 + aRow[rep] < M)
                ? *(const float4*)(A + (size_t)(m0 + aRow[rep]) * K + aKq[rep])
                : make_float4(0.f, 0.f, 0.f, 0.f);
        rB[rep] = *(const float4*)(W + (size_t)bK[rep] * Nc + n0 + bNq[rep]);
    }
#pragma unroll
    for (int rep = 0; rep < 2; rep++) {
        As[0][aKq[rep] + 0][aRow[rep]] = rA[rep].x;
        As[0][aKq[rep] + 1][aRow[rep]] = rA[rep].y;
        As[0][aKq[rep] + 2][aRow[rep]] = rA[rep].z;
        As[0][aKq[rep] + 3][aRow[rep]] = rA[rep].w;
        *(float4*)&Bs[0][bK[rep]][bNq[rep]] = rB[rep];
    }
    if (nTiles > 1) {
#pragma unroll
        for (int rep = 0; rep < 2; rep++) {
            rA[rep] = (m0 + aRow[rep] < M)
                    ? *(const float4*)(A + (size_t)(m0 + aRow[rep]) * K + 16 + aKq[rep])
                    : make_float4(0.f, 0.f, 0.f, 0.f);
            rB[rep] = *(const float4*)(W + (size_t)(16 + bK[rep]) * Nc + n0 + bNq[rep]);
        }
    }
    __syncthreads();

    for (int kt = 0; kt < nTiles; kt++) {
        int buf = kt & 1;
#pragma unroll
        for (int k = 0; k < 16; k++) {
            float4 a0 = *(float4*)&As[buf][k][warpM * 32 + lr * 4];
            float4 a1 = *(float4*)&As[buf][k][warpM * 32 + 16 + lr * 4];
            unsigned long long bp[2][2];
#pragma unroll
            for (int qn = 0; qn < 2; qn++) {
                const unsigned long long* b =
                    (const unsigned long long*)&Bs[buf][k][warpN * 64 + qn * 32 + lc * 4];
                bp[qn][0] = b[0];
                bp[qn][1] = b[1];
            }
            float av[2][4] = {{a0.x, a0.y, a0.z, a0.w}, {a1.x, a1.y, a1.z, a1.w}};
            unsigned long long aa[2][4];
#pragma unroll
            for (int qm = 0; qm < 2; qm++)
#pragma unroll
                for (int i = 0; i < 4; i++) {
                    unsigned int au = __float_as_uint(av[qm][i]);
                    asm("mov.b64 %0, {%1, %1};" : "=l"(aa[qm][i]) : "r"(au));
                }
#pragma unroll
            for (int qm = 0; qm < 2; qm++)
#pragma unroll
                for (int qn = 0; qn < 2; qn++)
#pragma unroll
                    for (int i = 0; i < 4; i++) {
                        asm("fma.rn.f32x2 %0, %1, %2, %0;"
                            : "+l"(acc[qm][qn][i][0])
                            : "l"(aa[qm][i]), "l"(bp[qn][0]));
                        asm("fma.rn.f32x2 %0, %1, %2, %0;"
                            : "+l"(acc[qm][qn][i][1])
                            : "l"(aa[qm][i]), "l"(bp[qn][1]));
                    }
        }
        if (kt + 1 < nTiles) {
            int nbuf = (kt + 1) & 1;
            __syncthreads();
#pragma unroll
            for (int rep = 0; rep < 2; rep++) {
                As[nbuf][aKq[rep] + 0][aRow[rep]] = rA[rep].x;
                As[nbuf][aKq[rep] + 1][aRow[rep]] = rA[rep].y;
                As[nbuf][aKq[rep] + 2][aRow[rep]] = rA[rep].z;
                As[nbuf][aKq[rep] + 3][aRow[rep]] = rA[rep].w;
                *(float4*)&Bs[nbuf][bK[rep]][bNq[rep]] = rB[rep];
            }
            if (kt + 2 < nTiles) {
                int k0 = (kt + 2) * 16;
#pragma unroll
                for (int rep = 0; rep < 2; rep++) {
                    rA[rep] = (m0 + aRow[rep] < M)
                            ? *(const float4*)(A + (size_t)(m0 + aRow[rep]) * K + k0 + aKq[rep])
                            : make_float4(0.f, 0.f, 0.f, 0.f);
                    rB[rep] = *(const float4*)(W + (size_t)(k0 + bK[rep]) * Nc + n0 + bNq[rep]);
                }
            }
            __syncthreads();
        }
    }

    float bcol[2][4];
#pragma unroll
    for (int qn = 0; qn < 2; qn++) {
        float4 bb = *(const float4*)(bias + n0 + warpN * 64 + qn * 32 + lc * 4);
        bcol[qn][0] = bb.x; bcol[qn][1] = bb.y; bcol[qn][2] = bb.z; bcol[qn][3] = bb.w;
    }
#pragma unroll
    for (int qm = 0; qm < 2; qm++)
#pragma unroll
        for (int i = 0; i < 4; i++) {
            int row = m0 + warpM * 32 + qm * 16 + lr * 4 + i;
            if (row < M) {
#pragma unroll
                for (int qn = 0; qn < 2; qn++) {
                    unsigned int l0, h0, l1, h1;
                    asm("mov.b64 {%0, %1}, %2;" : "=r"(l0), "=r"(h0)
                        : "l"(acc[qm][qn][i][0]));
                    asm("mov.b64 {%0, %1}, %2;" : "=r"(l1), "=r"(h1)
                        : "l"(acc[qm][qn][i][1]));
                    float4 o;
                    o.x = __uint_as_float(l0) + bcol[qn][0];
                    o.y = __uint_as_float(h0) + bcol[qn][1];
                    o.z = __uint_as_float(l1) + bcol[qn][2];
                    o.w = __uint_as_float(h1) + bcol[qn][3];
                    *(float4*)(C + (size_t)row * Nc + n0 + warpN * 64 + qn * 32 + lc * 4) = o;
                }
            }
        }
}

// ---------------- precompute: M_h = Wq_h @ Wk_h^T into W1cat -----------------
__global__ void build_m(const float* __restrict__ Wq, const float* __restrict__ Wk) {
    int l = blockIdx.x;
    const float* wq = Wq + (size_t)l * HID * HC;
    const float* wk = Wk + (size_t)l * HID * HC;
    float* w1 = g_w1 + (size_t)l * HID * 384;
#pragma unroll
    for (int j = 0; j < 8; j++) {
        int idx = blockIdx.y * 2048 + threadIdx.x * 8 + j;
        int h = idx >> 14, rem = idx & 16383;
        int r = rem >> 7, c = rem & 127;
        const float4* qr = (const float4*)(wq + r * HC + h * 128);
        const float4* kr = (const float4*)(wk + c * HC + h * 128);
        float s = 0.f;
#pragma unroll 8
        for (int o = 0; o < 32; o++) s += dot4(qr[o], kr[o]);
        w1[r * 384 + h * 128 + c] = s;
    }
}

// ---------------- precompute: W2cat, skip cols, biases, aux vectors ----------
__global__ void build_rest(const float* __restrict__ Wv, const float* __restrict__ Wskip,
                           const float* __restrict__ Wq, const float* __restrict__ Wk,
                           const float* __restrict__ Wee, const float* __restrict__ bq,
                           const float* __restrict__ bk, const float* __restrict__ bv,
                           const float* __restrict__ bskip) {
    int l = blockIdx.x, t = threadIdx.x;
    const float* wv  = Wv + (size_t)l * HID * HC;
    const float* ws  = Wskip + (size_t)l * HID * HID;
    const float* wq  = Wq + (size_t)l * HID * HC;
    const float* wk  = Wk + (size_t)l * HID * HC;
    const float* we  = Wee + (size_t)l * HC;
    const float* bql = bq + (size_t)l * HC;
    const float* bkl = bk + (size_t)l * HC;

    float* w2 = g_w2 + (size_t)l * HC * HID;
    for (int idx = t; idx < HC * HID; idx += 256) {
        int row = idx >> 7, c = idx & 127;
        int h = row >> 7, k = row & 127;
        w2[row * 128 + c] = 0.5f * wv[k * HC + h * 128 + c];
    }
    float* w1 = g_w1 + (size_t)l * HID * 384;
    for (int idx = t; idx < HID * HID; idx += 256) {
        int r = idx >> 7, c = idx & 127;
        w1[r * 384 + 256 + c] = ws[r * 128 + c];
    }
    if (t < 384) g_b1[l * 384 + t] = (t < 256) ? 0.f : bskip[l * HID + t - 256];
    for (int idx = t; idx < 3 * 2 * HID; idx += 256) {
        int which = idx / 256, rem = idx % 256;
        int h = rem >> 7, r = rem & 127;
        float s = 0.f;
        if (which == 0) {
            const float* a = wq + r * HC + h * 128;
            for (int o = 0; o < 128; o++) s += a[o] * we[h * 128 + o];
            g_uqe[l * 256 + rem] = s;
        } else if (which == 1) {
            const float* a = wq + r * HC + h * 128;
            for (int o = 0; o < 128; o++) s += a[o] * bkl[h * 128 + o];
            g_va[l * 256 + rem] = s;
        } else {
            const float* a = wk + r * HC + h * 128;
            for (int o = 0; o < 128; o++) s += a[o] * bql[h * 128 + o];
            g_vb[l * 256 + rem] = s;
        }
    }
    if (t < 128) g_bvm[l * 128 + t] = 0.5f * (bv[l * HC + t] + bv[l * HC + 128 + t]);
    if (t < 2) {
        float s0 = 0.f, s1 = 0.f;
        for (int o = 0; o < 128; o++) {
            s0 += bql[t * 128 + o] * bkl[t * 128 + o];
            s1 += bql[t * 128 + o] * we[t * 128 + o];
        }
        g_c0[l * 2 + t]  = s0;
        g_c1s[l * 2 + t] = s1;
    }
}

// ---------------- initial LayerNorm (+ bx for layer 0) -----------------------
__global__ void ln_init(const float* __restrict__ xin, const float* __restrict__ g,
                        const float* __restrict__ b, const float* __restrict__ vb,
                        float* __restrict__ xout, float* __restrict__ bx, int N) {
    int warp = (blockIdx.x * blockDim.x + threadIdx.x) >> 5;
    int lane = threadIdx.x & 31;
    if (warp >= N) return;
    float4 v = *(const float4*)(xin + (size_t)warp * 128 + lane * 4);
    float s = v.x + v.y + v.z + v.w;
#pragma unroll
    for (int o = 16; o; o >>= 1) s += __shfl_xor_sync(~0u, s, o);
    float mu = s * (1.f / 128.f);
    float d0 = v.x - mu, d1 = v.y - mu, d2 = v.z - mu, d3 = v.w - mu;
    float q = d0 * d0 + d1 * d1 + d2 * d2 + d3 * d3;
#pragma unroll
    for (int o = 16; o; o >>= 1) q += __shfl_xor_sync(~0u, q, o);
    float inv = rsqrtf(q * (1.f / 128.f) + 1e-5f);
    float4 gg = *(const float4*)(g + lane * 4);
    float4 bb = *(const float4*)(b + lane * 4);
    float4 out;
    out.x = d0 * inv * gg.x + bb.x;
    out.y = d1 * inv * gg.y + bb.y;
    out.z = d2 * inv * gg.z + bb.z;
    out.w = d3 * inv * gg.w + bb.w;
    *(float4*)(xout + (size_t)warp * 128 + lane * 4) = out;
    float4 v0 = *(const float4*)(vb + lane * 4);
    float4 v1 = *(const float4*)(vb + 128 + lane * 4);
    float p0 = dot4(out, v0), p1 = dot4(out, v1);
#pragma unroll
    for (int o = 16; o; o >>= 1) {
        p0 += __shfl_xor_sync(~0u, p0, o);
        p1 += __shfl_xor_sync(~0u, p1, o);
    }
    if (lane == 0) {
        bx[(size_t)warp * 2 + 0] = p0;
        bx[(size_t)warp * 2 + 1] = p1;
    }
}

// ---------------- CSR build --------------------------------------------------
__global__ void hist_kernel(const int* __restrict__ ei, int E) {
    int e = blockIdx.x * blockDim.x + threadIdx.x;
    if (e >= E) return;
    atomicAdd(&g_cnt[ei[(size_t)E + e]], 1);
}

__global__ void scan_kernel(int N) {
    __shared__ int sh[1024];
    int t = threadIdx.x;
    int chunk = (N + 1023) / 1024;
    int lo = t * chunk, hi = min(lo + chunk, N);
    int s = 0;
    for (int i = lo; i < hi; i++) s += g_cnt[i];
    sh[t] = s;
    __syncthreads();
    for (int off = 1; off < 1024; off <<= 1) {
        int v = (t >= off) ? sh[t - off] : 0;
        __syncthreads();
        sh[t] += v;
        __syncthreads();
    }
    int base = sh[t] - s;
    for (int i = lo; i < hi; i++) {
        g_off[i] = base;
        g_cur[i] = base;
        base += g_cnt[i];
    }
}

__global__ void scatter_kernel(const int* __restrict__ ei, const float* __restrict__ ea,
                               int E) {
    int e = blockIdx.x * blockDim.x + threadIdx.x;
    if (e >= E) return;
    int tgt = ei[(size_t)E + e];
    int pos = atomicAdd(&g_cur[tgt], 1);
    g_srcs[pos] = ei[e];
    g_eas[pos]  = ea[e];
}

// ---------------- degree sort (counting sort, 256 bins) ----------------------
__global__ void deg_hist(int N) {
    int n = blockIdx.x * blockDim.x + threadIdx.x;
    if (n >= N) return;
    atomicAdd(&g_dh[min(g_cnt[n], 255)], 1);
}

__global__ void deg_scan() {   // single block, 256 threads
    __shared__ int sh[256];
    int t = threadIdx.x;
    int v = g_dh[t];
    sh[t] = v;
    __syncthreads();
    for (int off = 1; off < 256; off <<= 1) {
        int u = (t >= off) ? sh[t - off] : 0;
        __syncthreads();
        sh[t] += u;
        __syncthreads();
    }
    g_dh[t] = sh[t] - v;   // exclusive prefix -> running cursor
}

__global__ void deg_scatter(int N) {
    int n = blockIdx.x * blockDim.x + threadIdx.x;
    if (n >= N) return;
    int pos = atomicAdd(&g_dh[min(g_cnt[n], 255)], 1);
    g_perm[pos] = n;
}

// ---------------- fused single-pass attention, 2-way interleave, deg-sorted --
__global__ void attn3(const float* __restrict__ x, const float* __restrict__ c1,
                      const float* __restrict__ uqe, const float* __restrict__ va,
                      const float* __restrict__ cc0, const float* __restrict__ cc1,
                      const float* __restrict__ bx, float* __restrict__ y,
                      float* __restrict__ sv, int N) {
    int widx = (blockIdx.x * blockDim.x + threadIdx.x) >> 5;
    int lane = threadIdx.x & 31;
    if (widx >= N) return;
    int n = g_perm[widx];        // degree-sorted schedule
    int hl = lane >> 4, sl = lane & 15, d0 = sl * 8;

    float4 xi0 = *(const float4*)(x + (size_t)n * 128 + d0);
    float4 xi1 = *(const float4*)(x + (size_t)n * 128 + d0 + 4);
    float4 z0  = *(const float4*)(c1 + (size_t)n * 384 + hl * 128 + d0);
    float4 z1  = *(const float4*)(c1 + (size_t)n * 384 + hl * 128 + d0 + 4);
    float4 u0  = *(const float4*)(uqe + hl * 128 + d0);
    float4 u1  = *(const float4*)(uqe + hl * 128 + d0 + 4);
    float4 a0v = *(const float4*)(va + hl * 128 + d0);
    float4 a1v = *(const float4*)(va + hl * 128 + d0 + 4);

    float pq = dot4(xi0, u0) + dot4(xi1, u1);
    float pa = dot4(xi0, a0v) + dot4(xi1, a1v);
#pragma unroll
    for (int o = 8; o; o >>= 1) {
        pq += __shfl_xor_sync(~0u, pq, o);
        pa += __shfl_xor_sync(~0u, pa, o);
    }
    float qwe = pq + cc1[hl];
    float ai  = pa + cc0[hl];

    int beg = g_off[n];
    int cnt = g_cnt[n];

    float den = 0.f, s = 0.f;
    float4 y0 = make_float4(0.f, 0.f, 0.f, 0.f);
    float4 y1 = make_float4(0.f, 0.f, 0.f, 0.f);

    int i = 0;
    for (; i + 2 <= cnt; i += 2) {
        int   ja = g_srcs[beg + i],     jb = g_srcs[beg + i + 1];
        float ea = g_eas[beg + i],      eb = g_eas[beg + i + 1];
        float4 xa0 = *(const float4*)(x + (size_t)ja * 128 + d0);
        float4 xa1 = *(const float4*)(x + (size_t)ja * 128 + d0 + 4);
        float4 xb0 = *(const float4*)(x + (size_t)jb * 128 + d0);
        float4 xb1 = *(const float4*)(x + (size_t)jb * 128 + d0 + 4);
        float da = dot4(z0, xa0) + dot4(z1, xa1);
        float db = dot4(z0, xb0) + dot4(z1, xb1);
#pragma unroll
        for (int o = 8; o; o >>= 1) {
            da += __shfl_xor_sync(~0u, da, o);
            db += __shfl_xor_sync(~0u, db, o);
        }
        float e0 = __expf((da + ai + bx[(size_t)ja * 2 + hl] + ea * qwe) * RSQRT_D);
        float e1 = __expf((db + ai + bx[(size_t)jb * 2 + hl] + eb * qwe) * RSQRT_D);
        den += e0;
        s += ea * e0;
        y0.x += e0 * xa0.x; y0.y += e0 * xa0.y; y0.z += e0 * xa0.z; y0.w += e0 * xa0.w;
        y1.x += e0 * xa1.x; y1.y += e0 * xa1.y; y1.z += e0 * xa1.z; y1.w += e0 * xa1.w;
        den += e1;
        s += eb * e1;
        y0.x += e1 * xb0.x; y0.y += e1 * xb0.y; y0.z += e1 * xb0.z; y0.w += e1 * xb0.w;
        y1.x += e1 * xb1.x; y1.y += e1 * xb1.y; y1.z += e1 * xb1.z; y1.w += e1 * xb1.w;
    }
    if (i < cnt) {
        int   j   = g_srcs[beg + i];
        float eav = g_eas[beg + i];
        float4 xj0 = *(const float4*)(x + (size_t)j * 128 + d0);
        float4 xj1 = *(const float4*)(x + (size_t)j * 128 + d0 + 4);
        float d = dot4(z0, xj0) + dot4(z1, xj1);
#pragma unroll
        for (int o = 8; o; o >>= 1) d += __shfl_xor_sync(~0u, d, o);
        float e = __expf((d + ai + bx[(size_t)j * 2 + hl] + eav * qwe) * RSQRT_D);
        den += e;
        s += eav * e;
        y0.x += e * xj0.x; y0.y += e * xj0.y; y0.z += e * xj0.z; y0.w += e * xj0.w;
        y1.x += e * xj1.x; y1.y += e * xj1.y; y1.z += e * xj1.z; y1.w += e * xj1.w;
    }
    float inv = (den > 0.f) ? 1.f / den : 1.f;
    y0.x *= inv; y0.y *= inv; y0.z *= inv; y0.w *= inv;
    y1.x *= inv; y1.y *= inv; y1.z *= inv; y1.w *= inv;
    *(float4*)(y + (size_t)n * HC + hl * 128 + d0)     = y0;
    *(float4*)(y + (size_t)n * HC + hl * 128 + d0 + 4) = y1;
    if (sl == 0) sv[(size_t)n * 2 + hl] = s * inv;
}

// ---------------- finalize: epilogue + LN (+ bx for next layer) --------------
__global__ void finalize2(const float* __restrict__ c2, const float* __restrict__ c1,
                          const float* __restrict__ We, const float* __restrict__ bvm,
                          const float* __restrict__ sv, const float* __restrict__ xin,
                          const float* __restrict__ lng, const float* __restrict__ lnb,
                          const float* __restrict__ vbn, float* __restrict__ xout,
                          float* __restrict__ bx, int N) {
    int n = (blockIdx.x * blockDim.x + threadIdx.x) >> 5;
    int lane = threadIdx.x & 31;
    if (n >= N) return;
    int c0 = lane * 4;
    float4 o4 = *(const float4*)(c2 + (size_t)n * 128 + c0);
    float s0 = sv[(size_t)n * 2], s1 = sv[(size_t)n * 2 + 1];
    float4 w0 = *(const float4*)(We + c0);
    float4 w1 = *(const float4*)(We + 128 + c0);
    float4 sk = *(const float4*)(c1 + (size_t)n * 384 + 256 + c0);
    float4 xo = *(const float4*)(xin + (size_t)n * 128 + c0);
    int cnt = g_cnt[n];
    float4 bv4 = make_float4(0.f, 0.f, 0.f, 0.f);
    if (cnt > 0) bv4 = *(const float4*)(bvm + c0);

    float o[4], t4[4];
    o[0] = o4.x + 0.5f * (w0.x * s0 + w1.x * s1) + bv4.x + sk.x;
    o[1] = o4.y + 0.5f * (w0.y * s0 + w1.y * s1) + bv4.y + sk.y;
    o[2] = o4.z + 0.5f * (w0.z * s0 + w1.z * s1) + bv4.z + sk.z;
    o[3] = o4.w + 0.5f * (w0.w * s0 + w1.w * s1) + bv4.w + sk.w;
    float xr[4] = {xo.x, xo.y, xo.z, xo.w};
#pragma unroll
    for (int j = 0; j < 4; j++) {
        float hlu = (o[j] > 0.f) ? o[j] : (expf(o[j]) - 1.f);  // ELU
        t4[j] = xr[j] + hlu;
    }
    float s = t4[0] + t4[1] + t4[2] + t4[3];
#pragma unroll
    for (int of = 16; of; of >>= 1) s += __shfl_xor_sync(~0u, s, of);
    float mu = s * (1.f / 128.f);
    float qv = 0.f;
#pragma unroll
    for (int j = 0; j < 4; j++) { float dd = t4[j] - mu; qv += dd * dd; }
#pragma unroll
    for (int of = 16; of; of >>= 1) qv += __shfl_xor_sync(~0u, qv, of);
    float inv = rsqrtf(qv * (1.f / 128.f) + 1e-5f);
    float4 gg = *(const float4*)(lng + c0);
    float4 bb = *(const float4*)(lnb + c0);
    float4 out;
    out.x = (t4[0] - mu) * inv * gg.x + bb.x;
    out.y = (t4[1] - mu) * inv * gg.y + bb.y;
    out.z = (t4[2] - mu) * inv * gg.z + bb.z;
    out.w = (t4[3] - mu) * inv * gg.w + bb.w;
    *(float4*)(xout + (size_t)n * 128 + c0) = out;
    float4 v0 = *(const float4*)(vbn + c0);
    float4 v1 = *(const float4*)(vbn + 128 + c0);
    float p0 = dot4(out, v0), p1 = dot4(out, v1);
#pragma unroll
    for (int of = 16; of; of >>= 1) {
        p0 += __shfl_xor_sync(~0u, p0, of);
        p1 += __shfl_xor_sync(~0u, p1, of);
    }
    if (lane == 0) {
        bx[(size_t)n * 2 + 0] = p0;
        bx[(size_t)n * 2 + 1] = p1;
    }
}

// ---------------- host launcher ---------------------------------------------
extern "C" void kernel_launch(void* const* d_in, const int* in_sizes, int n_in,
                              void* d_out, int out_size) {
    const float* x       = (const float*)d_in[0];
    const int*   ei      = (const int*)d_in[1];
    const float* ea      = (const float*)d_in[2];
    const float* ln_in_g = (const float*)d_in[3];
    const float* ln_in_b = (const float*)d_in[4];
    const float* Wq      = (const float*)d_in[5];
    const float* bq      = (const float*)d_in[6];
    const float* Wk      = (const float*)d_in[7];
    const float* bk      = (const float*)d_in[8];
    const float* Wv      = (const float*)d_in[9];
    const float* bv      = (const float*)d_in[10];
    const float* We      = (const float*)d_in[11];
    const float* Wskip   = (const float*)d_in[12];
    const float* bskip   = (const float*)d_in[13];
    const float* ln_g    = (const float*)d_in[14];
    const float* ln_b    = (const float*)d_in[15];

    int N = in_sizes[0] / HID;
    int E = in_sizes[1] / 2;

    float *pxa, *pxb, *pc1, *py, *pc2, *psv, *pbx;
    float *pw1, *pw2, *pb1, *puqe, *pva, *pvb, *pc0, *pc1s, *pbvm, *pbz;
    int *pcnt, *pdh;
    cudaGetSymbolAddress((void**)&pxa,  g_xa);
    cudaGetSymbolAddress((void**)&pxb,  g_xb);
    cudaGetSymbolAddress((void**)&pc1,  g_c1);
    cudaGetSymbolAddress((void**)&py,   g_y);
    cudaGetSymbolAddress((void**)&pc2,  g_c2);
    cudaGetSymbolAddress((void**)&psv,  g_sv);
    cudaGetSymbolAddress((void**)&pbx,  g_bx);
    cudaGetSymbolAddress((void**)&pw1,  g_w1);
    cudaGetSymbolAddress((void**)&pw2,  g_w2);
    cudaGetSymbolAddress((void**)&pb1,  g_b1);
    cudaGetSymbolAddress((void**)&puqe, g_uqe);
    cudaGetSymbolAddress((void**)&pva,  g_va);
    cudaGetSymbolAddress((void**)&pvb,  g_vb);
    cudaGetSymbolAddress((void**)&pc0,  g_c0);
    cudaGetSymbolAddress((void**)&pc1s, g_c1s);
    cudaGetSymbolAddress((void**)&pbvm, g_bvm);
    cudaGetSymbolAddress((void**)&pbz,  g_bzero);
    cudaGetSymbolAddress((void**)&pcnt, g_cnt);
    cudaGetSymbolAddress((void**)&pdh,  g_dh);

    int nodeBlocks = (N + 7) / 8;
    int eThreadBlocks = (E + 255) / 256;
    int nThreadBlocks = (N + 255) / 256;
    int mTiles = (N + 127) / 128;

    // Launch order keeps gemm128 as the 5th launch (ncu -s 5 -c 1 window).
    build_m<<<dim3(3, 16), 256>>>(Wq, Wk);                              // 1
    build_rest<<<3, 256>>>(Wv, Wskip, Wq, Wk, We, bq, bk, bv, bskip);   // 2
    ln_init<<<nodeBlocks, 256>>>(x, ln_in_g, ln_in_b, pvb, pxa, pbx, N);// 3
    cudaMemsetAsync(pcnt, 0, (size_t)N * sizeof(int));                  // 4
    gemm128<<<dim3(3, mTiles), 256>>>(pxa, pw1, pb1, pc1, N, 384, HID); // 5

    hist_kernel<<<eThreadBlocks, 256>>>(ei, E);
    scan_kernel<<<1, 1024>>>(N);
    scatter_kernel<<<eThreadBlocks, 256>>>(ei, ea, E);

    // degree-sorted node permutation for attention load balance
    cudaMemsetAsync(pdh, 0, 256 * sizeof(int));
    deg_hist<<<nThreadBlocks, 256>>>(N);
    deg_scan<<<1, 256>>>();
    deg_scatter<<<nThreadBlocks, 256>>>(N);

    float* xcur = pxa;
    float* xnxt = pxb;
    for (int l = 0; l < 3; l++) {
        const float* We_l = We + (size_t)l * HC;
        const float* lg_l = ln_g + (size_t)l * HID;
        const float* lb_l = ln_b + (size_t)l * HID;
        int lnext = (l < 2) ? l + 1 : l;
        float* xdst = (l == 2) ? (float*)d_out : xnxt;

        if (l > 0)
            gemm128<<<dim3(3, mTiles), 256>>>(xcur, pw1 + (size_t)l * HID * 384,
                                              pb1 + (size_t)l * 384, pc1, N, 384, HID);
        attn3<<<nodeBlocks, 256>>>(xcur, pc1, puqe + (size_t)l * 256,
                                   pva + (size_t)l * 256,
                                   pc0 + (size_t)l * 2, pc1s + (size_t)l * 2,
                                   pbx, py, psv, N);
        gemm128<<<dim3(1, mTiles), 256>>>(py, pw2 + (size_t)l * HC * HID,
                                          pbz, pc2, N, HID, HC);
        finalize2<<<nodeBlocks, 256>>>(pc2, pc1, We_l, pbvm + (size_t)l * HID,
                                       psv, xcur, lg_l, lb_l,
                                       pvb + (size_t)lnext * 256, xdst, pbx, N);
        float* tmp = xcur; xcur = xnxt; xnxt = tmp;
    }
}

// round 17
// speedup vs baseline: 1.0121x; 1.0121x over previous
#include <cuda_runtime.h>
#include <cstdint>
#include <cfloat>

#define NN 50000
#define NE 500000
#define HID 128
#define HC 256

// ---------------- scratch (static device globals; no allocation) -------------
__device__ float g_xa[(size_t)NN * HID];
__device__ float g_xb[(size_t)NN * HID];
__device__ float g_c1[(size_t)NN * 384];   // [z(256) | skip(128)]
__device__ float g_y[(size_t)NN * HC];     // aggregated weighted x per head
__device__ float g_c2[(size_t)NN * HID];   // y @ W2cat
__device__ float g_bx[(size_t)NN * 2];     // vb_h . x_n  (per-source bias dot)
__device__ float g_sv[(size_t)NN * 2];
__device__ int   g_cnt[NN];
__device__ int   g_off[NN];
__device__ int   g_cur[NN];
__device__ int   g_srcs[NE];
__device__ float g_eas[NE];

// precomputed (weights are launch-constant)
__device__ float g_w1[3 * HID * 384];      // [M_0 | M_1 | Wskip]
__device__ float g_w2[3 * HC * HID];       // 0.5*[Wv_0 ; Wv_1]
__device__ float g_b1[3 * 384];            // [0(256) | bskip]
__device__ float g_uqe[3 * 2 * HID];       // Wq_h @ We_h
__device__ float g_va[3 * 2 * HID];        // Wq_h @ bk_h
__device__ float g_vb[3 * 2 * HID];        // Wk_h @ bq_h
__device__ float g_c0[3 * 2];              // bq_h . bk_h
__device__ float g_c1s[3 * 2];             // bq_h . We_h
__device__ float g_bvm[3 * HID];           // 0.5*(bv_0 + bv_1)
__device__ float g_bzero[384];             // stays zero

#define RSQRT_D 0.08838834764831845f /* 1/sqrt(128) */

__device__ __forceinline__ float dot4(float4 a, float4 b) {
    return a.x * b.x + a.y * b.y + a.z * b.z + a.w * b.w;
}

// ---------------- GEMM: C[M,Nc] = A[M,K] @ W[K,Nc] + bias --------------------
// (R12/R15 configuration — measured best, frozen: 128x128 tile, 256 thr,
//  4x2 warp grid, 4x8 lanes, fp32x2 FMAs, register prefetch, stage-after-
//  compute double buffering with two barriers per tile)
__global__ __launch_bounds__(256, 2)
void gemm128(const float* __restrict__ A, const float* __restrict__ W,
             const float* __restrict__ bias, float* __restrict__ C,
             int M, int Nc, int K) {
    __shared__ float As[2][16][132];
    __shared__ float Bs[2][16][132];
    int t    = threadIdx.x;
    int lane = t & 31, warp = t >> 5;
    int warpM = warp >> 1, warpN = warp & 1;
    int lr = lane >> 3, lc = lane & 7;
    int m0 = blockIdx.y * 128, n0 = blockIdx.x * 128;
    int nTiles = K >> 4;

    unsigned long long acc[2][2][4][2];
#pragma unroll
    for (int qm = 0; qm < 2; qm++)
#pragma unroll
        for (int qn = 0; qn < 2; qn++)
#pragma unroll
            for (int i = 0; i < 4; i++) {
                acc[qm][qn][i][0] = 0ull;
                acc[qm][qn][i][1] = 0ull;
            }

    int aRow[2], aKq[2], bK[2], bNq[2];
#pragma unroll
    for (int rep = 0; rep < 2; rep++) {
        int idx = rep * 256 + t;
        aRow[rep] = idx >> 2;
        aKq[rep]  = (idx & 3) * 4;
        bK[rep]   = idx >> 5;
        bNq[rep]  = (idx & 31) * 4;
    }

    float4 rA[2], rB[2];
#pragma unroll
    for (int rep = 0; rep < 2; rep++) {
        rA[rep] = (m0 + aRow[rep] < M)
                ? *(const float4*)(A + (size_t)(m0 + aRow[rep]) * K + aKq[rep])
                : make_float4(0.f, 0.f, 0.f, 0.f);
        rB[rep] = *(const float4*)(W + (size_t)bK[rep] * Nc + n0 + bNq[rep]);
    }
#pragma unroll
    for (int rep = 0; rep < 2; rep++) {
        As[0][aKq[rep] + 0][aRow[rep]] = rA[rep].x;
        As[0][aKq[rep] + 1][aRow[rep]] = rA[rep].y;
        As[0][aKq[rep] + 2][aRow[rep]] = rA[rep].z;
        As[0][aKq[rep] + 3][aRow[rep]] = rA[rep].w;
        *(float4*)&Bs[0][bK[rep]][bNq[rep]] = rB[rep];
    }
    if (nTiles > 1) {
#pragma unroll
        for (int rep = 0; rep < 2; rep++) {
            rA[rep] = (m0 + aRow[rep] < M)
                    ? *(const float4*)(A + (size_t)(m0 + aRow[rep]) * K + 16 + aKq[rep])
                    : make_float4(0.f, 0.f, 0.f, 0.f);
            rB[rep] = *(const float4*)(W + (size_t)(16 + bK[rep]) * Nc + n0 + bNq[rep]);
        }
    }
    __syncthreads();

    for (int kt = 0; kt < nTiles; kt++) {
        int buf = kt & 1;
#pragma unroll
        for (int k = 0; k < 16; k++) {
            float4 a0 = *(float4*)&As[buf][k][warpM * 32 + lr * 4];
            float4 a1 = *(float4*)&As[buf][k][warpM * 32 + 16 + lr * 4];
            unsigned long long bp[2][2];
#pragma unroll
            for (int qn = 0; qn < 2; qn++) {
                const unsigned long long* b =
                    (const unsigned long long*)&Bs[buf][k][warpN * 64 + qn * 32 + lc * 4];
                bp[qn][0] = b[0];
                bp[qn][1] = b[1];
            }
            float av[2][4] = {{a0.x, a0.y, a0.z, a0.w}, {a1.x, a1.y, a1.z, a1.w}};
            unsigned long long aa[2][4];
#pragma unroll
            for (int qm = 0; qm < 2; qm++)
#pragma unroll
                for (int i = 0; i < 4; i++) {
                    unsigned int au = __float_as_uint(av[qm][i]);
                    asm("mov.b64 %0, {%1, %1};" : "=l"(aa[qm][i]) : "r"(au));
                }
#pragma unroll
            for (int qm = 0; qm < 2; qm++)
#pragma unroll
                for (int qn = 0; qn < 2; qn++)
#pragma unroll
                    for (int i = 0; i < 4; i++) {
                        asm("fma.rn.f32x2 %0, %1, %2, %0;"
                            : "+l"(acc[qm][qn][i][0])
                            : "l"(aa[qm][i]), "l"(bp[qn][0]));
                        asm("fma.rn.f32x2 %0, %1, %2, %0;"
                            : "+l"(acc[qm][qn][i][1])
                            : "l"(aa[qm][i]), "l"(bp[qn][1]));
                    }
        }
        if (kt + 1 < nTiles) {
            int nbuf = (kt + 1) & 1;
            __syncthreads();
#pragma unroll
            for (int rep = 0; rep < 2; rep++) {
                As[nbuf][aKq[rep] + 0][aRow[rep]] = rA[rep].x;
                As[nbuf][aKq[rep] + 1][aRow[rep]] = rA[rep].y;
                As[nbuf][aKq[rep] + 2][aRow[rep]] = rA[rep].z;
                As[nbuf][aKq[rep] + 3][aRow[rep]] = rA[rep].w;
                *(float4*)&Bs[nbuf][bK[rep]][bNq[rep]] = rB[rep];
            }
            if (kt + 2 < nTiles) {
                int k0 = (kt + 2) * 16;
#pragma unroll
                for (int rep = 0; rep < 2; rep++) {
                    rA[rep] = (m0 + aRow[rep] < M)
                            ? *(const float4*)(A + (size_t)(m0 + aRow[rep]) * K + k0 + aKq[rep])
                            : make_float4(0.f, 0.f, 0.f, 0.f);
                    rB[rep] = *(const float4*)(W + (size_t)(k0 + bK[rep]) * Nc + n0 + bNq[rep]);
                }
            }
            __syncthreads();
        }
    }

    float bcol[2][4];
#pragma unroll
    for (int qn = 0; qn < 2; qn++) {
        float4 bb = *(const float4*)(bias + n0 + warpN * 64 + qn * 32 + lc * 4);
        bcol[qn][0] = bb.x; bcol[qn][1] = bb.y; bcol[qn][2] = bb.z; bcol[qn][3] = bb.w;
    }
#pragma unroll
    for (int qm = 0; qm < 2; qm++)
#pragma unroll
        for (int i = 0; i < 4; i++) {
            int row = m0 + warpM * 32 + qm * 16 + lr * 4 + i;
            if (row < M) {
#pragma unroll
                for (int qn = 0; qn < 2; qn++) {
                    unsigned int l0, h0, l1, h1;
                    asm("mov.b64 {%0, %1}, %2;" : "=r"(l0), "=r"(h0)
                        : "l"(acc[qm][qn][i][0]));
                    asm("mov.b64 {%0, %1}, %2;" : "=r"(l1), "=r"(h1)
                        : "l"(acc[qm][qn][i][1]));
                    float4 o;
                    o.x = __uint_as_float(l0) + bcol[qn][0];
                    o.y = __uint_as_float(h0) + bcol[qn][1];
                    o.z = __uint_as_float(l1) + bcol[qn][2];
                    o.w = __uint_as_float(h1) + bcol[qn][3];
                    *(float4*)(C + (size_t)row * Nc + n0 + warpN * 64 + qn * 32 + lc * 4) = o;
                }
            }
        }
}

// ---------------- precompute: M_h = Wq_h @ Wk_h^T into W1cat -----------------
__global__ void build_m(const float* __restrict__ Wq, const float* __restrict__ Wk) {
    int l = blockIdx.x;
    const float* wq = Wq + (size_t)l * HID * HC;
    const float* wk = Wk + (size_t)l * HID * HC;
    float* w1 = g_w1 + (size_t)l * HID * 384;
#pragma unroll
    for (int j = 0; j < 8; j++) {
        int idx = blockIdx.y * 2048 + threadIdx.x * 8 + j;
        int h = idx >> 14, rem = idx & 16383;
        int r = rem >> 7, c = rem & 127;
        const float4* qr = (const float4*)(wq + r * HC + h * 128);
        const float4* kr = (const float4*)(wk + c * HC + h * 128);
        float s = 0.f;
#pragma unroll 8
        for (int o = 0; o < 32; o++) s += dot4(qr[o], kr[o]);
        w1[r * 384 + h * 128 + c] = s;
    }
}

// ---------------- precompute: W2cat, skip cols, biases, aux vectors ----------
__global__ void build_rest(const float* __restrict__ Wv, const float* __restrict__ Wskip,
                           const float* __restrict__ Wq, const float* __restrict__ Wk,
                           const float* __restrict__ Wee, const float* __restrict__ bq,
                           const float* __restrict__ bk, const float* __restrict__ bv,
                           const float* __restrict__ bskip) {
    int l = blockIdx.x, t = threadIdx.x;
    const float* wv  = Wv + (size_t)l * HID * HC;
    const float* ws  = Wskip + (size_t)l * HID * HID;
    const float* wq  = Wq + (size_t)l * HID * HC;
    const float* wk  = Wk + (size_t)l * HID * HC;
    const float* we  = Wee + (size_t)l * HC;
    const float* bql = bq + (size_t)l * HC;
    const float* bkl = bk + (size_t)l * HC;

    float* w2 = g_w2 + (size_t)l * HC * HID;
    for (int idx = t; idx < HC * HID; idx += 256) {
        int row = idx >> 7, c = idx & 127;
        int h = row >> 7, k = row & 127;
        w2[row * 128 + c] = 0.5f * wv[k * HC + h * 128 + c];
    }
    float* w1 = g_w1 + (size_t)l * HID * 384;
    for (int idx = t; idx < HID * HID; idx += 256) {
        int r = idx >> 7, c = idx & 127;
        w1[r * 384 + 256 + c] = ws[r * 128 + c];
    }
    if (t < 384) g_b1[l * 384 + t] = (t < 256) ? 0.f : bskip[l * HID + t - 256];
    for (int idx = t; idx < 3 * 2 * HID; idx += 256) {
        int which = idx / 256, rem = idx % 256;
        int h = rem >> 7, r = rem & 127;
        float s = 0.f;
        if (which == 0) {
            const float* a = wq + r * HC + h * 128;
            for (int o = 0; o < 128; o++) s += a[o] * we[h * 128 + o];
            g_uqe[l * 256 + rem] = s;
        } else if (which == 1) {
            const float* a = wq + r * HC + h * 128;
            for (int o = 0; o < 128; o++) s += a[o] * bkl[h * 128 + o];
            g_va[l * 256 + rem] = s;
        } else {
            const float* a = wk + r * HC + h * 128;
            for (int o = 0; o < 128; o++) s += a[o] * bql[h * 128 + o];
            g_vb[l * 256 + rem] = s;
        }
    }
    if (t < 128) g_bvm[l * 128 + t] = 0.5f * (bv[l * HC + t] + bv[l * HC + 128 + t]);
    if (t < 2) {
        float s0 = 0.f, s1 = 0.f;
        for (int o = 0; o < 128; o++) {
            s0 += bql[t * 128 + o] * bkl[t * 128 + o];
            s1 += bql[t * 128 + o] * we[t * 128 + o];
        }
        g_c0[l * 2 + t]  = s0;
        g_c1s[l * 2 + t] = s1;
    }
}

// ---------------- initial LayerNorm (+ bx for layer 0) -----------------------
__global__ void ln_init(const float* __restrict__ xin, const float* __restrict__ g,
                        const float* __restrict__ b, const float* __restrict__ vb,
                        float* __restrict__ xout, float* __restrict__ bx, int N) {
    int warp = (blockIdx.x * blockDim.x + threadIdx.x) >> 5;
    int lane = threadIdx.x & 31;
    if (warp >= N) return;
    float4 v = *(const float4*)(xin + (size_t)warp * 128 + lane * 4);
    float s = v.x + v.y + v.z + v.w;
#pragma unroll
    for (int o = 16; o; o >>= 1) s += __shfl_xor_sync(~0u, s, o);
    float mu = s * (1.f / 128.f);
    float d0 = v.x - mu, d1 = v.y - mu, d2 = v.z - mu, d3 = v.w - mu;
    float q = d0 * d0 + d1 * d1 + d2 * d2 + d3 * d3;
#pragma unroll
    for (int o = 16; o; o >>= 1) q += __shfl_xor_sync(~0u, q, o);
    float inv = rsqrtf(q * (1.f / 128.f) + 1e-5f);
    float4 gg = *(const float4*)(g + lane * 4);
    float4 bb = *(const float4*)(b + lane * 4);
    float4 out;
    out.x = d0 * inv * gg.x + bb.x;
    out.y = d1 * inv * gg.y + bb.y;
    out.z = d2 * inv * gg.z + bb.z;
    out.w = d3 * inv * gg.w + bb.w;
    *(float4*)(xout + (size_t)warp * 128 + lane * 4) = out;
    float4 v0 = *(const float4*)(vb + lane * 4);
    float4 v1 = *(const float4*)(vb + 128 + lane * 4);
    float p0 = dot4(out, v0), p1 = dot4(out, v1);
#pragma unroll
    for (int o = 16; o; o >>= 1) {
        p0 += __shfl_xor_sync(~0u, p0, o);
        p1 += __shfl_xor_sync(~0u, p1, o);
    }
    if (lane == 0) {
        bx[(size_t)warp * 2 + 0] = p0;
        bx[(size_t)warp * 2 + 1] = p1;
    }
}

// ---------------- CSR build --------------------------------------------------
__global__ void hist_kernel(const int* __restrict__ ei, int E) {
    int e = blockIdx.x * blockDim.x + threadIdx.x;
    if (e >= E) return;
    atomicAdd(&g_cnt[ei[(size_t)E + e]], 1);
}

__global__ void scan_kernel(int N) {
    __shared__ int sh[1024];
    int t = threadIdx.x;
    int chunk = (N + 1023) / 1024;
    int lo = t * chunk, hi = min(lo + chunk, N);
    int s = 0;
    for (int i = lo; i < hi; i++) s += g_cnt[i];
    sh[t] = s;
    __syncthreads();
    for (int off = 1; off < 1024; off <<= 1) {
        int v = (t >= off) ? sh[t - off] : 0;
        __syncthreads();
        sh[t] += v;
        __syncthreads();
    }
    int base = sh[t] - s;
    for (int i = lo; i < hi; i++) {
        g_off[i] = base;
        g_cur[i] = base;
        base += g_cnt[i];
    }
}

__global__ void scatter_kernel(const int* __restrict__ ei, const float* __restrict__ ea,
                               int E) {
    int e = blockIdx.x * blockDim.x + threadIdx.x;
    if (e >= E) return;
    int tgt = ei[(size_t)E + e];
    int pos = atomicAdd(&g_cur[tgt], 1);
    g_srcs[pos] = ei[e];
    g_eas[pos]  = ea[e];
}

// ---------------- fused single-pass attention, 2-way edge interleave ---------
__global__ void attn3(const float* __restrict__ x, const float* __restrict__ c1,
                      const float* __restrict__ uqe, const float* __restrict__ va,
                      const float* __restrict__ cc0, const float* __restrict__ cc1,
                      const float* __restrict__ bx, float* __restrict__ y,
                      float* __restrict__ sv, int N) {
    int n = (blockIdx.x * blockDim.x + threadIdx.x) >> 5;
    int lane = threadIdx.x & 31;
    if (n >= N) return;
    int hl = lane >> 4, sl = lane & 15, d0 = sl * 8;

    float4 xi0 = *(const float4*)(x + (size_t)n * 128 + d0);
    float4 xi1 = *(const float4*)(x + (size_t)n * 128 + d0 + 4);
    float4 z0  = *(const float4*)(c1 + (size_t)n * 384 + hl * 128 + d0);
    float4 z1  = *(const float4*)(c1 + (size_t)n * 384 + hl * 128 + d0 + 4);
    float4 u0  = *(const float4*)(uqe + hl * 128 + d0);
    float4 u1  = *(const float4*)(uqe + hl * 128 + d0 + 4);
    float4 a0v = *(const float4*)(va + hl * 128 + d0);
    float4 a1v = *(const float4*)(va + hl * 128 + d0 + 4);

    float pq = dot4(xi0, u0) + dot4(xi1, u1);
    float pa = dot4(xi0, a0v) + dot4(xi1, a1v);
#pragma unroll
    for (int o = 8; o; o >>= 1) {
        pq += __shfl_xor_sync(~0u, pq, o);
        pa += __shfl_xor_sync(~0u, pa, o);
    }
    float qwe = pq + cc1[hl];
    float ai  = pa + cc0[hl];

    int beg = g_off[n];
    int cnt = g_cnt[n];

    float den = 0.f, s = 0.f;
    float4 y0 = make_float4(0.f, 0.f, 0.f, 0.f);
    float4 y1 = make_float4(0.f, 0.f, 0.f, 0.f);

    int i = 0;
    for (; i + 2 <= cnt; i += 2) {
        int   ja = g_srcs[beg + i],     jb = g_srcs[beg + i + 1];
        float ea = g_eas[beg + i],      eb = g_eas[beg + i + 1];
        float4 xa0 = *(const float4*)(x + (size_t)ja * 128 + d0);
        float4 xa1 = *(const float4*)(x + (size_t)ja * 128 + d0 + 4);
        float4 xb0 = *(const float4*)(x + (size_t)jb * 128 + d0);
        float4 xb1 = *(const float4*)(x + (size_t)jb * 128 + d0 + 4);
        float da = dot4(z0, xa0) + dot4(z1, xa1);
        float db = dot4(z0, xb0) + dot4(z1, xb1);
#pragma unroll
        for (int o = 8; o; o >>= 1) {
            da += __shfl_xor_sync(~0u, da, o);
            db += __shfl_xor_sync(~0u, db, o);
        }
        float e0 = __expf((da + ai + bx[(size_t)ja * 2 + hl] + ea * qwe) * RSQRT_D);
        float e1 = __expf((db + ai + bx[(size_t)jb * 2 + hl] + eb * qwe) * RSQRT_D);
        den += e0;
        s += ea * e0;
        y0.x += e0 * xa0.x; y0.y += e0 * xa0.y; y0.z += e0 * xa0.z; y0.w += e0 * xa0.w;
        y1.x += e0 * xa1.x; y1.y += e0 * xa1.y; y1.z += e0 * xa1.z; y1.w += e0 * xa1.w;
        den += e1;
        s += eb * e1;
        y0.x += e1 * xb0.x; y0.y += e1 * xb0.y; y0.z += e1 * xb0.z; y0.w += e1 * xb0.w;
        y1.x += e1 * xb1.x; y1.y += e1 * xb1.y; y1.z += e1 * xb1.z; y1.w += e1 * xb1.w;
    }
    if (i < cnt) {
        int   j   = g_srcs[beg + i];
        float eav = g_eas[beg + i];
        float4 xj0 = *(const float4*)(x + (size_t)j * 128 + d0);
        float4 xj1 = *(const float4*)(x + (size_t)j * 128 + d0 + 4);
        float d = dot4(z0, xj0) + dot4(z1, xj1);
#pragma unroll
        for (int o = 8; o; o >>= 1) d += __shfl_xor_sync(~0u, d, o);
        float e = __expf((d + ai + bx[(size_t)j * 2 + hl] + eav * qwe) * RSQRT_D);
        den += e;
        s += eav * e;
        y0.x += e * xj0.x; y0.y += e * xj0.y; y0.z += e * xj0.z; y0.w += e * xj0.w;
        y1.x += e * xj1.x; y1.y += e * xj1.y; y1.z += e * xj1.z; y1.w += e * xj1.w;
    }
    float inv = (den > 0.f) ? 1.f / den : 1.f;
    y0.x *= inv; y0.y *= inv; y0.z *= inv; y0.w *= inv;
    y1.x *= inv; y1.y *= inv; y1.z *= inv; y1.w *= inv;
    *(float4*)(y + (size_t)n * HC + hl * 128 + d0)     = y0;
    *(float4*)(y + (size_t)n * HC + hl * 128 + d0 + 4) = y1;
    if (sl == 0) sv[(size_t)n * 2 + hl] = s * inv;
}

// ---------------- finalize: epilogue + LN (+ bx for next layer if any) -------
__global__ void finalize2(const float* __restrict__ c2, const float* __restrict__ c1,
                          const float* __restrict__ We, const float* __restrict__ bvm,
                          const float* __restrict__ sv, const float* __restrict__ xin,
                          const float* __restrict__ lng, const float* __restrict__ lnb,
                          const float* __restrict__ vbn, float* __restrict__ xout,
                          float* __restrict__ bx, int N) {
    int n = (blockIdx.x * blockDim.x + threadIdx.x) >> 5;
    int lane = threadIdx.x & 31;
    if (n >= N) return;
    int c0 = lane * 4;
    float4 o4 = *(const float4*)(c2 + (size_t)n * 128 + c0);
    float s0 = sv[(size_t)n * 2], s1 = sv[(size_t)n * 2 + 1];
    float4 w0 = *(const float4*)(We + c0);
    float4 w1 = *(const float4*)(We + 128 + c0);
    float4 sk = *(const float4*)(c1 + (size_t)n * 384 + 256 + c0);
    float4 xo = *(const float4*)(xin + (size_t)n * 128 + c0);
    int cnt = g_cnt[n];
    float4 bv4 = make_float4(0.f, 0.f, 0.f, 0.f);
    if (cnt > 0) bv4 = *(const float4*)(bvm + c0);

    float o[4], t4[4];
    o[0] = o4.x + 0.5f * (w0.x * s0 + w1.x * s1) + bv4.x + sk.x;
    o[1] = o4.y + 0.5f * (w0.y * s0 + w1.y * s1) + bv4.y + sk.y;
    o[2] = o4.z + 0.5f * (w0.z * s0 + w1.z * s1) + bv4.z + sk.z;
    o[3] = o4.w + 0.5f * (w0.w * s0 + w1.w * s1) + bv4.w + sk.w;
    float xr[4] = {xo.x, xo.y, xo.z, xo.w};
#pragma unroll
    for (int j = 0; j < 4; j++) {
        float hlu = (o[j] > 0.f) ? o[j] : (expf(o[j]) - 1.f);  // ELU
        t4[j] = xr[j] + hlu;
    }
    float s = t4[0] + t4[1] + t4[2] + t4[3];
#pragma unroll
    for (int of = 16; of; of >>= 1) s += __shfl_xor_sync(~0u, s, of);
    float mu = s * (1.f / 128.f);
    float qv = 0.f;
#pragma unroll
    for (int j = 0; j < 4; j++) { float dd = t4[j] - mu; qv += dd * dd; }
#pragma unroll
    for (int of = 16; of; of >>= 1) qv += __shfl_xor_sync(~0u, qv, of);
    float inv = rsqrtf(qv * (1.f / 128.f) + 1e-5f);
    float4 gg = *(const float4*)(lng + c0);
    float4 bb = *(const float4*)(lnb + c0);
    float4 out;
    out.x = (t4[0] - mu) * inv * gg.x + bb.x;
    out.y = (t4[1] - mu) * inv * gg.y + bb.y;
    out.z = (t4[2] - mu) * inv * gg.z + bb.z;
    out.w = (t4[3] - mu) * inv * gg.w + bb.w;
    *(float4*)(xout + (size_t)n * 128 + c0) = out;
    if (vbn) {   // no next layer -> skip bx production
        float4 v0 = *(const float4*)(vbn + c0);
        float4 v1 = *(const float4*)(vbn + 128 + c0);
        float p0 = dot4(out, v0), p1 = dot4(out, v1);
#pragma unroll
        for (int of = 16; of; of >>= 1) {
            p0 += __shfl_xor_sync(~0u, p0, of);
            p1 += __shfl_xor_sync(~0u, p1, of);
        }
        if (lane == 0) {
            bx[(size_t)n * 2 + 0] = p0;
            bx[(size_t)n * 2 + 1] = p1;
        }
    }
}

// ---------------- host launcher ---------------------------------------------
extern "C" void kernel_launch(void* const* d_in, const int* in_sizes, int n_in,
                              void* d_out, int out_size) {
    const float* x       = (const float*)d_in[0];
    const int*   ei      = (const int*)d_in[1];
    const float* ea      = (const float*)d_in[2];
    const float* ln_in_g = (const float*)d_in[3];
    const float* ln_in_b = (const float*)d_in[4];
    const float* Wq      = (const float*)d_in[5];
    const float* bq      = (const float*)d_in[6];
    const float* Wk      = (const float*)d_in[7];
    const float* bk      = (const float*)d_in[8];
    const float* Wv      = (const float*)d_in[9];
    const float* bv      = (const float*)d_in[10];
    const float* We      = (const float*)d_in[11];
    const float* Wskip   = (const float*)d_in[12];
    const float* bskip   = (const float*)d_in[13];
    const float* ln_g    = (const float*)d_in[14];
    const float* ln_b    = (const float*)d_in[15];

    int N = in_sizes[0] / HID;
    int E = in_sizes[1] / 2;

    float *pxa, *pxb, *pc1, *py, *pc2, *psv, *pbx;
    float *pw1, *pw2, *pb1, *puqe, *pva, *pvb, *pc0, *pc1s, *pbvm, *pbz;
    int* pcnt;
    cudaGetSymbolAddress((void**)&pxa,  g_xa);
    cudaGetSymbolAddress((void**)&pxb,  g_xb);
    cudaGetSymbolAddress((void**)&pc1,  g_c1);
    cudaGetSymbolAddress((void**)&py,   g_y);
    cudaGetSymbolAddress((void**)&pc2,  g_c2);
    cudaGetSymbolAddress((void**)&psv,  g_sv);
    cudaGetSymbolAddress((void**)&pbx,  g_bx);
    cudaGetSymbolAddress((void**)&pw1,  g_w1);
    cudaGetSymbolAddress((void**)&pw2,  g_w2);
    cudaGetSymbolAddress((void**)&pb1,  g_b1);
    cudaGetSymbolAddress((void**)&puqe, g_uqe);
    cudaGetSymbolAddress((void**)&pva,  g_va);
    cudaGetSymbolAddress((void**)&pvb,  g_vb);
    cudaGetSymbolAddress((void**)&pc0,  g_c0);
    cudaGetSymbolAddress((void**)&pc1s, g_c1s);
    cudaGetSymbolAddress((void**)&pbvm, g_bvm);
    cudaGetSymbolAddress((void**)&pbz,  g_bzero);
    cudaGetSymbolAddress((void**)&pcnt, g_cnt);

    int nodeBlocks = (N + 7) / 8;
    int eThreadBlocks = (E + 255) / 256;
    int mTiles = (N + 127) / 128;

    // Launch order keeps gemm128 as the 5th launch (ncu -s 5 -c 1 window).
    build_m<<<dim3(3, 16), 256>>>(Wq, Wk);                              // 1
    build_rest<<<3, 256>>>(Wv, Wskip, Wq, Wk, We, bq, bk, bv, bskip);   // 2
    ln_init<<<nodeBlocks, 256>>>(x, ln_in_g, ln_in_b, pvb, pxa, pbx, N);// 3
    cudaMemsetAsync(pcnt, 0, (size_t)N * sizeof(int));                  // 4
    gemm128<<<dim3(3, mTiles), 256>>>(pxa, pw1, pb1, pc1, N, 384, HID); // 5

    hist_kernel<<<eThreadBlocks, 256>>>(ei, E);
    scan_kernel<<<1, 1024>>>(N);
    scatter_kernel<<<eThreadBlocks, 256>>>(ei, ea, E);

    float* xcur = pxa;
    float* xnxt = pxb;
    for (int l = 0; l < 3; l++) {
        const float* We_l = We + (size_t)l * HC;
        const float* lg_l = ln_g + (size_t)l * HID;
        const float* lb_l = ln_b + (size_t)l * HID;
        float* xdst = (l == 2) ? (float*)d_out : xnxt;
        const float* vbn_l = (l < 2) ? (pvb + (size_t)(l + 1) * 256) : nullptr;

        if (l > 0)
            gemm128<<<dim3(3, mTiles), 256>>>(xcur, pw1 + (size_t)l * HID * 384,
                                              pb1 + (size_t)l * 384, pc1, N, 384, HID);
        attn3<<<nodeBlocks, 256>>>(xcur, pc1, puqe + (size_t)l * 256,
                                   pva + (size_t)l * 256,
                                   pc0 + (size_t)l * 2, pc1s + (size_t)l * 2,
                                   pbx, py, psv, N);
        gemm128<<<dim3(1, mTiles), 256>>>(py, pw2 + (size_t)l * HC * HID,
                                          pbz, pc2, N, HID, HC);
        finalize2<<<nodeBlocks, 256>>>(pc2, pc1, We_l, pbvm + (size_t)l * HID,
                                       psv, xcur, lg_l, lb_l,
                                       vbn_l, xdst, pbx, N);
        float* tmp = xcur; xcur = xnxt; xnxt = tmp;
    }
}